// round 9
// baseline (speedup 1.0000x reference)
#include <cuda_runtime.h>
#include <cuda_bf16.h>
#include <cstdint>

// ---------------- problem constants ----------------
#define D      512
#define NTOT   32768            // 8*4096 samples
#define MT     128              // unit tile M
#define NT     64               // unit tile N
#define KC     64               // k per smem stage
#define SPLITS 16
#define KSP    (NTOT / SPLITS)  // 2048
#define NCHUNK (KSP / KC)       // 32
#define NJOBS  52               // 32 HL tiles + 20 upper HH tiles
#define NUNITS (NJOBS * SPLITS) // 832

// ---------------- device scratch (no allocation) ----------------
__device__ __nv_bfloat16 g_Ht[(size_t)D * NTOT];   // 32 MB K-major hi
__device__ __nv_bfloat16 g_Lt[(size_t)D * NTOT];   // 32 MB K-major lo
__device__ float g_hh[D * D];                      // H^T H (upper tiles only)
__device__ float g_hl[D * D];                      // H^T L (full)
__device__ float g_ps2[8 * NTOT];                  // per-(dblock,sample) sum x^2
__device__ float g_ps4[8 * NTOT];                  // per-(dblock,sample) sum x^4

// HH upper-tile list: tiles (iT,jT) with jT*64+64 > iT*128
__constant__ int c_hhI[20] = {0,0,0,0,0,0,0,0,1,1,1,1,1,1,2,2,2,2,3,3};
__constant__ int c_hhJ[20] = {0,1,2,3,4,5,6,7,2,3,4,5,6,7,4,5,6,7,6,7};

__device__ __forceinline__ uint32_t smem_to_u32(const void* p) {
    uint32_t a;
    asm("{ .reg .u64 t; cvta.to.shared.u64 t, %1; cvt.u32.u64 %0, t; }" : "=r"(a) : "l"(p));
    return a;
}

// ---------------- kernel 1: transpose + hi/lo split + loss partials + zero ----
__global__ void __launch_bounds__(256) convert_kernel(const float* __restrict__ x) {
    __shared__ float tile[64][65];
    const int n0  = blockIdx.x * 64;
    const int db  = blockIdx.y;
    const int d0  = db * 64;
    const int tid = threadIdx.x;

    // zero scratch accumulators (1 MB each spread over the y==0 / y==1 slices)
    if (db == 0) {
        int base = blockIdx.x * 512 + tid;
        g_hh[base] = 0.0f; g_hh[base + 256] = 0.0f;
    } else if (db == 1) {
        int base = blockIdx.x * 512 + tid;
        g_hl[base] = 0.0f; g_hl[base + 256] = 0.0f;
    }

    const int r  = tid >> 4;
    const int c4 = (tid & 15) * 4;
    float s2[4] = {0.f, 0.f, 0.f, 0.f};
    float s4[4] = {0.f, 0.f, 0.f, 0.f};
#pragma unroll
    for (int p = 0; p < 4; ++p) {
        int n = p * 16 + r;
        float4 v = *reinterpret_cast<const float4*>(x + (size_t)(n0 + n) * D + d0 + c4);
        tile[n][c4 + 0] = v.x; tile[n][c4 + 1] = v.y;
        tile[n][c4 + 2] = v.z; tile[n][c4 + 3] = v.w;
        float a = v.x * v.x, b = v.y * v.y, c = v.z * v.z, d = v.w * v.w;
        s2[p] += a + b + c + d;
        s4[p] += a * a + b * b + c * c + d * d;
    }
    __syncthreads();
    const int dd = tid >> 2;
    const int nb = (tid & 3) * 16;
    __align__(16) __nv_bfloat16 hi[16];
    __align__(16) __nv_bfloat16 lo[16];
#pragma unroll
    for (int u = 0; u < 16; ++u) {
        float v = tile[nb + u][dd];
        __nv_bfloat16 h = __float2bfloat16(v);
        hi[u] = h;
        lo[u] = __float2bfloat16(v - __bfloat162float(h));
    }
    size_t base = (size_t)(d0 + dd) * NTOT + (size_t)(n0 + nb);
    *reinterpret_cast<uint4*>(&g_Ht[base])     = *reinterpret_cast<uint4*>(hi);
    *reinterpret_cast<uint4*>(&g_Ht[base + 8]) = *reinterpret_cast<uint4*>(hi + 8);
    *reinterpret_cast<uint4*>(&g_Lt[base])     = *reinterpret_cast<uint4*>(lo);
    *reinterpret_cast<uint4*>(&g_Lt[base + 8]) = *reinterpret_cast<uint4*>(lo + 8);

    // reduce loss partials across the 16 lanes sharing each row (within half-warp)
#pragma unroll
    for (int o = 8; o > 0; o >>= 1)
#pragma unroll
        for (int p = 0; p < 4; ++p) {
            s2[p] += __shfl_xor_sync(0xFFFFFFFFu, s2[p], o);
            s4[p] += __shfl_xor_sync(0xFFFFFFFFu, s4[p], o);
        }
    if ((tid & 15) == 0) {
#pragma unroll
        for (int p = 0; p < 4; ++p) {
            int n = n0 + p * 16 + r;
            g_ps2[db * NTOT + n] = s2[p];
            g_ps4[db * NTOT + n] = s4[p];
        }
    }
}

// ---------------- kernel 2: mma.sync gram, uniform work units ----------------
// Unit = (job, ksplit). job<32: HL tile (iT=job>>3, jT=job&7), B=Lt, dst=g_hl.
// job>=32: HH upper tile from c_hh lists, B=Ht, dst=g_hh.
// CTA 128 threads, 4 warps of 64x32. Single atomic per cell.
#define A_AREA 0
#define B_AREA 16384
#define STAGE_BYTES 24576
#define SMEM_BYTES (2 * STAGE_BYTES)   // 49152

__device__ __forceinline__ uint32_t sw128(uint32_t off) {
    return off ^ ((off >> 3) & 0x70);
}
__device__ __forceinline__ void cp16(uint32_t saddr, const void* gaddr) {
    asm volatile("cp.async.cg.shared.global [%0], [%1], 16;" :: "r"(saddr), "l"(gaddr));
}
__device__ __forceinline__ void cp_commit() {
    asm volatile("cp.async.commit_group;" ::: "memory");
}
template <int N>
__device__ __forceinline__ void cp_wait() {
    asm volatile("cp.async.wait_group %0;" :: "n"(N) : "memory");
}
__device__ __forceinline__ void ldsm_x4(uint32_t* r, uint32_t addr) {
    asm volatile("ldmatrix.sync.aligned.m8n8.x4.shared.b16 {%0,%1,%2,%3}, [%4];"
                 : "=r"(r[0]), "=r"(r[1]), "=r"(r[2]), "=r"(r[3]) : "r"(addr));
}
__device__ __forceinline__ void mma_bf16(float* c, const uint32_t* a, const uint32_t* b) {
    asm volatile(
        "mma.sync.aligned.m16n8k16.row.col.f32.bf16.bf16.f32 "
        "{%0,%1,%2,%3}, {%4,%5,%6,%7}, {%8,%9}, {%0,%1,%2,%3};"
        : "+f"(c[0]), "+f"(c[1]), "+f"(c[2]), "+f"(c[3])
        : "r"(a[0]), "r"(a[1]), "r"(a[2]), "r"(a[3]), "r"(b[0]), "r"(b[1]));
}

__global__ void __launch_bounds__(128, 3) gram_mma_kernel() {
    extern __shared__ __align__(1024) char smem[];
    const uint32_t smem_u = smem_to_u32(smem);
    const int tid  = threadIdx.x;
    const int wid  = tid >> 5;
    const int lane = tid & 31;

    const int job = blockIdx.x >> 4;
    const int ksp = blockIdx.x & 15;
    int iT, jT;
    const __nv_bfloat16* bbase;
    float* dst;
    if (job < 32) { iT = job >> 3; jT = job & 7; bbase = g_Lt; dst = g_hl; }
    else { int h = job - 32; iT = c_hhI[h]; jT = c_hhJ[h]; bbase = g_Ht; dst = g_hh; }
    const int iBase = iT * MT;
    const int jBase = jT * NT;
    const int k0    = ksp * KSP;

    const int m0 = (wid & 1) * 64;
    const int n0 = (wid >> 1) * 32;
    const uint32_t a_off0 = (uint32_t)((m0 + (lane & 15)) * 128 + (lane >> 4) * 16);
    const int bj   = ((lane & 16) >> 1) + (lane & 7);
    const uint32_t b_colb = (uint32_t)((lane & 8) * 2);
    const uint32_t b_off0 = (uint32_t)((n0 + bj) * 128) + b_colb;

    float acc[4][4][4];
#pragma unroll
    for (int mf = 0; mf < 4; ++mf)
#pragma unroll
        for (int nf = 0; nf < 4; ++nf)
#pragma unroll
            for (int e = 0; e < 4; ++e) acc[mf][nf][e] = 0.f;

    // stage loader: 192 rows (128 A + 64 B) of 128B, 1536 cp16 / 128 thr = 12 each
    auto load_stage = [&](int stage, int kc) {
        const uint32_t sbase = smem_u + stage * STAGE_BYTES;
#pragma unroll
        for (int it = 0; it < 12; ++it) {
            int idx = it * 128 + tid;
            int row = idx >> 3;
            int sub = idx & 7;
            const __nv_bfloat16* src;
            uint32_t area;
            int lr;
            if (row < MT) { lr = row;      src = g_Ht + (size_t)(iBase + lr) * NTOT; area = A_AREA; }
            else          { lr = row - MT; src = bbase + (size_t)(jBase + lr) * NTOT; area = B_AREA; }
            uint32_t off = sw128((uint32_t)(lr * 128 + sub * 16));
            cp16(sbase + area + off, src + kc + sub * 8);
        }
    };

    load_stage(0, k0);
    cp_commit();

    for (int c = 0; c < NCHUNK; ++c) {
        if (c + 1 < NCHUNK) {
            load_stage((c + 1) & 1, k0 + (c + 1) * KC);
            cp_commit();
            cp_wait<1>();
        } else {
            cp_wait<0>();
        }
        __syncthreads();

        const uint32_t sbase = smem_u + (c & 1) * STAGE_BYTES;
#pragma unroll
        for (int ks = 0; ks < KC / 16; ++ks) {
            const uint32_t kshift = (uint32_t)(ks * 32);
            uint32_t a[4][4], b[2][4];
#pragma unroll
            for (int mf = 0; mf < 4; ++mf)
                ldsm_x4(a[mf], sbase + A_AREA + sw128(a_off0 + (uint32_t)(mf * 2048) + kshift));
#pragma unroll
            for (int np = 0; np < 2; ++np)
                ldsm_x4(b[np], sbase + B_AREA + sw128(b_off0 + (uint32_t)(np * 2048) + kshift));
#pragma unroll
            for (int mf = 0; mf < 4; ++mf)
#pragma unroll
                for (int np = 0; np < 2; ++np) {
                    mma_bf16(acc[mf][np * 2 + 0], a[mf], &b[np][0]);
                    mma_bf16(acc[mf][np * 2 + 1], a[mf], &b[np][2]);
                }
        }
        __syncthreads();
    }

    // epilogue: ONE atomic per cell into g_hh or g_hl
    const int g = lane >> 2;
    const int t = lane & 3;
#pragma unroll
    for (int mf = 0; mf < 4; ++mf)
#pragma unroll
        for (int nf = 0; nf < 4; ++nf)
#pragma unroll
            for (int e = 0; e < 4; ++e) {
                int i = iBase + m0 + mf * 16 + g + (e >> 1) * 8;
                int j = jBase + n0 + nf * 8 + 2 * t + (e & 1);
                atomicAdd(&dst[i * D + j], acc[mf][nf][e]);
            }
}

// ---------------- kernel 3: finalize (grad assembly + loss reduction) --------
__global__ void __launch_bounds__(256) finalize_kernel(const float* __restrict__ kappa_p,
                                                       float* __restrict__ out) {
    if (blockIdx.x == 0) {
        // block 0: reduce loss partials
        const int tid = threadIdx.x;
        double lc = 0.0, lw = 0.0;
        for (int n = tid; n < NTOT; n += 256) {
            float s2 = 0.f, s4 = 0.f;
#pragma unroll
            for (int db = 0; db < 8; ++db) {
                s2 += g_ps2[db * NTOT + n];
                s4 += g_ps4[db * NTOT + n];
            }
            double d2 = (double)s2, d4 = (double)s4;
            lc += d2 * d2 - d4;
            lw += d4 - 2.0 * d2 + (double)D;
        }
        __shared__ double sc[256], sw2[256];
        sc[tid] = lc; sw2[tid] = lw;
        __syncthreads();
        for (int o = 128; o > 0; o >>= 1) {
            if (tid < o) { sc[tid] += sc[tid + o]; sw2[tid] += sw2[tid + o]; }
            __syncthreads();
        }
        if (tid == 0) {
            double scale = 1.0 / ((double)NTOT * (double)D * (double)D);
            out[D * D]     = (float)(sc[0] * scale);
            out[D * D + 1] = (float)(sw2[0] * scale);
        }
    } else {
        int idx = (blockIdx.x - 1) * 256 + threadIdx.x;
        int i = idx >> 9;
        int j = idx & (D - 1);
        // tile(i,j) HH-skipped iff jBase+64 <= iBase
        bool skij = ((j & ~63) + 64) <= (i & ~127);
        float hh = skij ? g_hh[j * D + i] : g_hh[idx];
        float m  = (hh + g_hl[idx] + g_hl[j * D + i]) * (1.0f / (float)NTOT);
        float kappa = *kappa_p;
        out[idx] = (i == j) ? kappa * (m - 1.0f) : (1.0f - kappa) * m;
    }
}

extern "C" void kernel_launch(void* const* d_in, const int* in_sizes, int n_in,
                              void* d_out, int out_size) {
    const float* x     = (const float*)d_in[0];
    const float* kappa = (const float*)d_in[1];
    float*       out   = (float*)d_out;

    cudaFuncSetAttribute(gram_mma_kernel, cudaFuncAttributeMaxDynamicSharedMemorySize, SMEM_BYTES);

    convert_kernel<<<dim3(NTOT / 64, D / 64), 256>>>(x);
    gram_mma_kernel<<<NUNITS, 128, SMEM_BYTES>>>();
    finalize_kernel<<<1 + (D * D) / 256, 256>>>(kappa, out);
}